// round 6
// baseline (speedup 1.0000x reference)
#include <cuda_runtime.h>
#include <cuda_bf16.h>
#include <math.h>
#include <stdint.h>

#define D_MODEL 1024
#define NHEADS  16
#define DHEAD   64
#define BATCH   2
#define SEQ     2048
#define MROWS   (BATCH*SEQ)          // 4096
#define BHTOT   (BATCH*NHEADS)       // 32
#define DD      (D_MODEL*D_MODEL)

// ---------------- scratch (no allocations allowed) ----------------
__device__ __nv_bfloat16 g_xh[(size_t)MROWS*D_MODEL], g_xl[(size_t)MROWS*D_MODEL];
__device__ __nv_bfloat16 g_Wh[(size_t)4*DD],          g_Wl[(size_t)4*DD];
__device__ __nv_bfloat16 g_Qh[(size_t)BHTOT*SEQ*DHEAD], g_Ql[(size_t)BHTOT*SEQ*DHEAD];
__device__ __nv_bfloat16 g_Kh[(size_t)BHTOT*SEQ*DHEAD], g_Kl[(size_t)BHTOT*SEQ*DHEAD];
__device__ __nv_bfloat16 g_Vh[(size_t)BHTOT*SEQ*DHEAD], g_Vl[(size_t)BHTOT*SEQ*DHEAD];
__device__ __nv_bfloat16 g_Oh[(size_t)MROWS*D_MODEL],   g_Ol[(size_t)MROWS*D_MODEL];

// =====================================================================
// helpers
// =====================================================================
__device__ __forceinline__ uint32_t smem_u32(const void* p) {
    uint32_t a;
    asm("{ .reg .u64 t; cvta.to.shared.u64 t, %1; cvt.u32.u64 %0, t; }"
        : "=r"(a) : "l"(p));
    return a;
}
__device__ __forceinline__ void ldsm4(uint32_t r[4], uint32_t a) {
    asm volatile("ldmatrix.sync.aligned.m8n8.x4.shared.b16 {%0,%1,%2,%3}, [%4];"
                 : "=r"(r[0]), "=r"(r[1]), "=r"(r[2]), "=r"(r[3]) : "r"(a));
}
__device__ __forceinline__ void ldsm4t(uint32_t r[4], uint32_t a) {
    asm volatile("ldmatrix.sync.aligned.m8n8.x4.trans.shared.b16 {%0,%1,%2,%3}, [%4];"
                 : "=r"(r[0]), "=r"(r[1]), "=r"(r[2]), "=r"(r[3]) : "r"(a));
}
__device__ __forceinline__ void mma_bf16(float d[4], const uint32_t a[4],
                                         uint32_t b0, uint32_t b1) {
    asm volatile(
        "mma.sync.aligned.m16n8k16.row.col.f32.bf16.bf16.f32 "
        "{%0,%1,%2,%3}, {%4,%5,%6,%7}, {%8,%9}, {%0,%1,%2,%3};"
        : "+f"(d[0]), "+f"(d[1]), "+f"(d[2]), "+f"(d[3])
        : "r"(a[0]), "r"(a[1]), "r"(a[2]), "r"(a[3]), "r"(b0), "r"(b1));
}
__device__ __forceinline__ void split2(float v0, float v1, uint32_t& hi, uint32_t& lo) {
    __nv_bfloat16 h0 = __float2bfloat16(v0);
    __nv_bfloat16 h1 = __float2bfloat16(v1);
    __nv_bfloat162 H = __halves2bfloat162(h0, h1);
    hi = *reinterpret_cast<uint32_t*>(&H);
    __nv_bfloat162 L = __floats2bfloat162_rn(v0 - __bfloat162float(h0),
                                             v1 - __bfloat162float(h1));
    lo = *reinterpret_cast<uint32_t*>(&L);
}
#define CPA16(dst, src) \
    asm volatile("cp.async.cg.shared.global [%0], [%1], 16;" \
                 :: "r"(dst), "l"(src) : "memory")
#define CPA_COMMIT() asm volatile("cp.async.commit_group;" ::: "memory")
#define CPA_WAIT0()  asm volatile("cp.async.wait_group 0;" ::: "memory")

// =====================================================================
// split kernels: fp32 -> (bf16 hi, bf16 lo), vectorized x4
// =====================================================================
__global__ void split4_kernel(const float* __restrict__ in,
                              __nv_bfloat16* __restrict__ hi,
                              __nv_bfloat16* __restrict__ lo, int n4)
{
    const int i = blockIdx.x * blockDim.x + threadIdx.x;
    if (i >= n4) return;
    const float4 v = ((const float4*)in)[i];
    uint32_t h0, l0, h1, l1;
    split2(v.x, v.y, h0, l0);
    split2(v.z, v.w, h1, l1);
    ((uint2*)hi)[i] = make_uint2(h0, h1);
    ((uint2*)lo)[i] = make_uint2(l0, l1);
}

__global__ void splitW_kernel(const float* __restrict__ W0, const float* __restrict__ W1,
                              const float* __restrict__ W2, const float* __restrict__ W3,
                              __nv_bfloat16* __restrict__ hi, __nv_bfloat16* __restrict__ lo)
{
    const int z = blockIdx.y;
    const float* in = (z == 0) ? W0 : (z == 1) ? W1 : (z == 2) ? W2 : W3;
    const size_t off4 = ((size_t)z * DD) / 4;
    const int i = blockIdx.x * blockDim.x + threadIdx.x;   // < DD/4
    const float4 v = ((const float4*)in)[i];
    uint32_t h0, l0, h1, l1;
    split2(v.x, v.y, h0, l0);
    split2(v.z, v.w, h1, l1);
    ((uint2*)hi)[off4 + i] = make_uint2(h0, h1);
    ((uint2*)lo)[off4 + i] = make_uint2(l0, l1);
}

// =====================================================================
// GEMM mainloop (shared): C[128,128] tile of A[M,1024] @ W[N,1024]^T
// pre-split bf16 inputs, cp.async double-buffered, BK=32.
// =====================================================================
#define GSTB   80
#define GA_SZ  (128*GSTB)          // 10240
#define GSTAGE (4*GA_SZ)           // 40960
#define GEMM_SMEM (2*GSTAGE)       // 81920

__device__ __forceinline__ void gemm_mainloop(
    const __nv_bfloat16* __restrict__ Ah, const __nv_bfloat16* __restrict__ Al,
    const __nv_bfloat16* __restrict__ Bh, const __nv_bfloat16* __restrict__ Bl,
    int m0, int n0, uint32_t sbase, float acc[2][8][4])
{
    const int tid = threadIdx.x;
    const int lane = tid & 31, wid = tid >> 5;
    const int wm = wid & 3, wn = wid >> 2;
    const uint32_t lrq = (lane & 15);
    const uint32_t lch = ((lane >> 4) << 3) * 2;

    const int c0 = tid * 2;
    const int row0 = c0 >> 2,      col0 = (c0 & 3);
    const int row1 = (c0+1) >> 2,  col1 = ((c0+1) & 3);

    auto issue = [&](int s, int buf) {
        const int k0 = s * 32;
        const uint32_t dst = sbase + buf * GSTAGE;
        {
            const uint32_t d0 = dst + row0*GSTB + col0*16;
            const size_t ea = (size_t)(m0 + row0) * 1024 + k0 + col0*8;
            const size_t eb = (size_t)(n0 + row0) * 1024 + k0 + col0*8;
            CPA16(d0,           Ah + ea);
            CPA16(d0 +   GA_SZ, Al + ea);
            CPA16(d0 + 2*GA_SZ, Bh + eb);
            CPA16(d0 + 3*GA_SZ, Bl + eb);
        }
        {
            const uint32_t d0 = dst + row1*GSTB + col1*16;
            const size_t ea = (size_t)(m0 + row1) * 1024 + k0 + col1*8;
            const size_t eb = (size_t)(n0 + row1) * 1024 + k0 + col1*8;
            CPA16(d0,           Ah + ea);
            CPA16(d0 +   GA_SZ, Al + ea);
            CPA16(d0 + 2*GA_SZ, Bh + eb);
            CPA16(d0 + 3*GA_SZ, Bl + eb);
        }
    };

    issue(0, 0);
    CPA_COMMIT();
    CPA_WAIT0();
    __syncthreads();

    for (int s = 0; s < 32; s++) {
        const int buf = s & 1;
        if (s < 31) { issue(s + 1, buf ^ 1); CPA_COMMIT(); }

        const uint32_t sA = sbase + buf * GSTAGE;
        const uint32_t sB = sA + 2*GA_SZ;
        #pragma unroll
        for (int kk = 0; kk < 2; kk++) {
            uint32_t ah[2][4], al[2][4];
            #pragma unroll
            for (int mi = 0; mi < 2; mi++) {
                const uint32_t addr = sA + (wm*32 + mi*16 + lrq)*GSTB + kk*32 + lch;
                ldsm4(ah[mi], addr);
                ldsm4(al[mi], addr + GA_SZ);
            }
            #pragma unroll
            for (int g = 0; g < 4; g++) {
                uint32_t bh[4], bl[4];
                const uint32_t baddr = sB + (wn*64 + g*16 + lrq)*GSTB + kk*32 + lch;
                ldsm4(bh, baddr);
                ldsm4(bl, baddr + GA_SZ);
                #pragma unroll
                for (int mi = 0; mi < 2; mi++) {
                    mma_bf16(acc[mi][2*g],   ah[mi], bh[0], bh[2]);
                    mma_bf16(acc[mi][2*g+1], ah[mi], bh[1], bh[3]);
                    mma_bf16(acc[mi][2*g],   ah[mi], bl[0], bl[2]);
                    mma_bf16(acc[mi][2*g+1], ah[mi], bl[1], bl[3]);
                    mma_bf16(acc[mi][2*g],   al[mi], bh[0], bh[2]);
                    mma_bf16(acc[mi][2*g+1], al[mi], bh[1], bh[3]);
                }
            }
        }
        if (s < 31) CPA_WAIT0();
        __syncthreads();
    }
}

// =====================================================================
// QKV GEMM (2 CTAs/SM):
//   z=0 -> Q: rope applied in-register, written as split bf16 [B,H,S,Dh]
//   z=1 -> K: same
//   z=2 -> V: split bf16 [B,H,S,Dh]
// =====================================================================
#define ROPE_L2B 0.41524101186091903f   // log2(10000)/32

__global__ __launch_bounds__(256, 2)
void gemm_qkv(const __nv_bfloat16* __restrict__ xh, const __nv_bfloat16* __restrict__ xl,
              const __nv_bfloat16* __restrict__ Wh, const __nv_bfloat16* __restrict__ Wl,
              const float* __restrict__ bQ, const float* __restrict__ bK,
              const float* __restrict__ bV,
              __nv_bfloat16* __restrict__ Qh, __nv_bfloat16* __restrict__ Ql,
              __nv_bfloat16* __restrict__ Kh, __nv_bfloat16* __restrict__ Kl,
              __nv_bfloat16* __restrict__ Vh, __nv_bfloat16* __restrict__ Vl)
{
    extern __shared__ char smraw[];
    const uint32_t sbase = smem_u32(smraw);
    const int z = blockIdx.z;
    const int m0 = blockIdx.y * 128, n0 = blockIdx.x * 128;
    const __nv_bfloat16* Whp = Wh + (size_t)z * DD;
    const __nv_bfloat16* Wlp = Wl + (size_t)z * DD;
    const float* bias = (z == 0) ? bQ : (z == 1) ? bK : bV;

    float acc[2][8][4] = {};
    gemm_mainloop(xh, xl, Whp, Wlp, m0, n0, sbase, acc);

    const int lane = threadIdx.x & 31, wid = threadIdx.x >> 5;
    const int wm = wid & 3, wn = wid >> 2;
    const int rbase = m0 + wm*32 + (lane >> 2);
    const int cbase = n0 + wn*64 + (lane & 3)*2;

    if (z == 2) {
        // ---- V: plain bias + split ----
        #pragma unroll
        for (int mi = 0; mi < 2; mi++) {
            #pragma unroll
            for (int j = 0; j < 8; j++) {
                const int c = cbase + j*8;
                const float2 b2 = *(const float2*)(bias + c);
                const int r0 = rbase + mi*16, r1 = r0 + 8;
                const int h = c >> 6, d = c & 63;
                const int b0b = r0 >> 11, s0 = r0 & (SEQ-1);
                const int b1b = r1 >> 11, s1 = r1 & (SEQ-1);
                const size_t i0 = (((size_t)(b0b*NHEADS + h)*SEQ + s0) << 6) + d;
                const size_t i1 = (((size_t)(b1b*NHEADS + h)*SEQ + s1) << 6) + d;
                uint32_t hi, lo;
                split2(acc[mi][j][0] + b2.x, acc[mi][j][1] + b2.y, hi, lo);
                *(uint32_t*)(Vh + i0) = hi;
                *(uint32_t*)(Vl + i0) = lo;
                split2(acc[mi][j][2] + b2.x, acc[mi][j][3] + b2.y, hi, lo);
                *(uint32_t*)(Vh + i1) = hi;
                *(uint32_t*)(Vl + i1) = lo;
            }
        }
    } else {
        // ---- Q/K: in-register RoPE, then split ----
        __nv_bfloat16* Xh = (z == 0) ? Qh : Kh;
        __nv_bfloat16* Xl = (z == 0) ? Ql : Kl;
        #pragma unroll
        for (int mi = 0; mi < 2; mi++) {
            #pragma unroll
            for (int rr = 0; rr < 2; rr++) {
                const int r  = rbase + mi*16 + rr*8;
                const int ss = r & (SEQ-1);
                const int bb = r >> 11;
                const float sf = (float)ss;
                #pragma unroll
                for (int j = 0; j < 4; j++) {
                    const int c = cbase + j*8;
                    const int h = c >> 6;
                    const int d = c & 63;           // in [0,32)
                    const float a  = acc[mi][j][rr*2+0]   + bias[c];
                    const float b  = acc[mi][j][rr*2+1]   + bias[c+1];
                    const float pa = acc[mi][j+4][rr*2+0] + bias[c+32];
                    const float pb = acc[mi][j+4][rr*2+1] + bias[c+33];
                    float s0, c0, s1, c1;
                    sincosf(sf * exp2f(-(float)d       * ROPE_L2B), &s0, &c0);
                    sincosf(sf * exp2f(-(float)(d + 1) * ROPE_L2B), &s1, &c1);
                    const float ya = a*c0  - pa*s0, yb = b*c1  - pb*s1;
                    const float za = pa*c0 + a*s0,  zb = pb*c1 + b*s1;
                    const size_t base = (((size_t)(bb*NHEADS + h)*SEQ + ss) << 6) + d;
                    uint32_t hi, lo;
                    split2(ya, yb, hi, lo);
                    *(uint32_t*)(Xh + base) = hi;
                    *(uint32_t*)(Xl + base) = lo;
                    split2(za, zb, hi, lo);
                    *(uint32_t*)(Xh + base + 32) = hi;
                    *(uint32_t*)(Xl + base + 32) = lo;
                }
            }
        }
    }
}

// =====================================================================
// Output GEMM (2 CTAs/SM): out = O @ Wo^T + bo (fp32 row-major)
// =====================================================================
__global__ __launch_bounds__(256, 2)
void gemm_out(const __nv_bfloat16* __restrict__ Oh, const __nv_bfloat16* __restrict__ Ol,
              const __nv_bfloat16* __restrict__ Wh, const __nv_bfloat16* __restrict__ Wl,
              const float* __restrict__ bias, float* __restrict__ out)
{
    extern __shared__ char smraw[];
    const uint32_t sbase = smem_u32(smraw);
    const int m0 = blockIdx.y * 128, n0 = blockIdx.x * 128;

    float acc[2][8][4] = {};
    gemm_mainloop(Oh, Ol, Wh, Wl, m0, n0, sbase, acc);

    const int lane = threadIdx.x & 31, wid = threadIdx.x >> 5;
    const int wm = wid & 3, wn = wid >> 2;
    const int rbase = m0 + wm*32 + (lane >> 2);
    const int cbase = n0 + wn*64 + (lane & 3)*2;
    #pragma unroll
    for (int mi = 0; mi < 2; mi++) {
        #pragma unroll
        for (int j = 0; j < 8; j++) {
            const int c = cbase + j*8;
            const float2 b2 = *(const float2*)(bias + c);
            const int r0 = rbase + mi*16, r1 = r0 + 8;
            *(float2*)(out + (size_t)r0 * D_MODEL + c) =
                make_float2(acc[mi][j][0] + b2.x, acc[mi][j][1] + b2.y);
            *(float2*)(out + (size_t)r1 * D_MODEL + c) =
                make_float2(acc[mi][j][2] + b2.x, acc[mi][j][3] + b2.y);
        }
    }
}

// =====================================================================
// Flash attention (2 CTAs/SM) on pre-split bf16; Q frags in regs;
// cp.async KV; output split bf16. CTA = (bh, 128 q rows).
// =====================================================================
#define ASTRB 144
#define AK_SZ (64*ASTRB)          // 9216 per matrix-half
#define ABUF  (4*AK_SZ)           // 36864 (Kh,Kl,Vh,Vl)
#define ATTN_SMEM (2*ABUF)        // 73728

__global__ __launch_bounds__(256, 2)
void attn_mma(const __nv_bfloat16* __restrict__ Qh_g, const __nv_bfloat16* __restrict__ Ql_g,
              const __nv_bfloat16* __restrict__ Kh_g, const __nv_bfloat16* __restrict__ Kl_g,
              const __nv_bfloat16* __restrict__ Vh_g, const __nv_bfloat16* __restrict__ Vl_g,
              __nv_bfloat16* __restrict__ Oh_g, __nv_bfloat16* __restrict__ Ol_g)
{
    extern __shared__ char sm[];
    const uint32_t sbase = smem_u32(sm);
    const int tid = threadIdx.x, wid = tid >> 5, lane = tid & 31;
    const int qb  = gridDim.x - 1 - blockIdx.x;
    const int bh  = blockIdx.y;
    const int qs  = qb * 128;

    const size_t bhoff = (size_t)bh * SEQ * DHEAD;
    const __nv_bfloat16* Khp = Kh_g + bhoff;
    const __nv_bfloat16* Klp = Kl_g + bhoff;
    const __nv_bfloat16* Vhp = Vh_g + bhoff;
    const __nv_bfloat16* Vlp = Vl_g + bhoff;

    const uint32_t lrq = (lane & 15);
    const uint32_t lch = ((lane >> 4) << 3) * 2;

    // ---- Q fragments direct from global (mma A-fragment lane map) ----
    uint32_t qh[4][4], ql[4][4];
    {
        const __nv_bfloat16* Qhp = Qh_g + bhoff;
        const __nv_bfloat16* Qlp = Ql_g + bhoff;
        const int r0 = qs + wid*16 + (lane >> 2);
        const int cq = (lane & 3) * 2;
        #pragma unroll
        for (int kk = 0; kk < 4; kk++) {
            const int c = kk*16 + cq;
            const size_t e00 = (size_t)r0 * 64 + c;
            const size_t e10 = (size_t)(r0 + 8) * 64 + c;
            qh[kk][0] = *(const uint32_t*)(Qhp + e00);
            qh[kk][1] = *(const uint32_t*)(Qhp + e10);
            qh[kk][2] = *(const uint32_t*)(Qhp + e00 + 8);
            qh[kk][3] = *(const uint32_t*)(Qhp + e10 + 8);
            ql[kk][0] = *(const uint32_t*)(Qlp + e00);
            ql[kk][1] = *(const uint32_t*)(Qlp + e10);
            ql[kk][2] = *(const uint32_t*)(Qlp + e00 + 8);
            ql[kk][3] = *(const uint32_t*)(Qlp + e10 + 8);
        }
    }

    // KV loader chunk map
    const int ch0 = tid*2, ch1 = tid*2 + 1;
    const int kr0 = ch0 >> 3, kc0 = ch0 & 7;
    const int kr1 = ch1 >> 3, kc1 = ch1 & 7;

    auto issueKV = [&](int t, int buf) {
        const int ks = t * 64;
        const uint32_t dst = sbase + buf * ABUF;
        {
            const uint32_t d0 = dst + kr0*ASTRB + kc0*16;
            const size_t  s0 = ((size_t)(ks + kr0)) * 64 + kc0*8;
            CPA16(d0,           Khp + s0);
            CPA16(d0 +   AK_SZ, Klp + s0);
            CPA16(d0 + 2*AK_SZ, Vhp + s0);
            CPA16(d0 + 3*AK_SZ, Vlp + s0);
        }
        {
            const uint32_t d0 = dst + kr1*ASTRB + kc1*16;
            const size_t  s0 = ((size_t)(ks + kr1)) * 64 + kc1*8;
            CPA16(d0,           Khp + s0);
            CPA16(d0 +   AK_SZ, Klp + s0);
            CPA16(d0 + 2*AK_SZ, Vhp + s0);
            CPA16(d0 + 3*AK_SZ, Vlp + s0);
        }
    };

    float o[8][4] = {};
    float m0r = -1e30f, m1r = -1e30f, l0r = 0.f, l1r = 0.f;
    const int nt = 2*(qb + 1);

    issueKV(0, 0);
    CPA_COMMIT();
    CPA_WAIT0();
    __syncthreads();

    for (int t = 0; t < nt; t++) {
        const int buf = t & 1;
        const int ks  = t * 64;
        if (t + 1 < nt) { issueKV(t + 1, buf ^ 1); CPA_COMMIT(); }

        if (qs + wid*16 + 15 >= ks) {
            const uint32_t sKh = sbase + buf * ABUF;
            const uint32_t sVh = sKh + 2*AK_SZ;

            // ---- S = Q K^T ----
            float s[8][4] = {};
            #pragma unroll
            for (int kk = 0; kk < 4; kk++) {
                #pragma unroll
                for (int g = 0; g < 4; g++) {
                    uint32_t khf[4], klf[4];
                    const uint32_t kaddr = sKh + (g*16 + lrq)*ASTRB + kk*32 + lch;
                    ldsm4(khf, kaddr);
                    ldsm4(klf, kaddr + AK_SZ);
                    mma_bf16(s[2*g],   qh[kk], khf[0], khf[2]);
                    mma_bf16(s[2*g+1], qh[kk], khf[1], khf[3]);
                    mma_bf16(s[2*g],   qh[kk], klf[0], klf[2]);
                    mma_bf16(s[2*g+1], qh[kk], klf[1], klf[3]);
                    mma_bf16(s[2*g],   ql[kk], khf[0], khf[2]);
                    mma_bf16(s[2*g+1], ql[kk], khf[1], khf[3]);
                }
            }

            // ---- scale + causal mask ----
            const int r0 = qs + wid*16 + (lane >> 2);
            const int r1 = r0 + 8;
            const float SC = 0.125f;
            if (ks + 63 > qs + wid*16) {
                #pragma unroll
                for (int j = 0; j < 8; j++) {
                    const int c = ks + j*8 + (lane & 3)*2;
                    s[j][0] = (c     <= r0) ? s[j][0]*SC : -1e30f;
                    s[j][1] = (c + 1 <= r0) ? s[j][1]*SC : -1e30f;
                    s[j][2] = (c     <= r1) ? s[j][2]*SC : -1e30f;
                    s[j][3] = (c + 1 <= r1) ? s[j][3]*SC : -1e30f;
                }
            } else {
                #pragma unroll
                for (int j = 0; j < 8; j++) {
                    s[j][0] *= SC; s[j][1] *= SC; s[j][2] *= SC; s[j][3] *= SC;
                }
            }

            // ---- online softmax ----
            float mx0 = -1e30f, mx1 = -1e30f;
            #pragma unroll
            for (int j = 0; j < 8; j++) {
                mx0 = fmaxf(mx0, fmaxf(s[j][0], s[j][1]));
                mx1 = fmaxf(mx1, fmaxf(s[j][2], s[j][3]));
            }
            mx0 = fmaxf(mx0, __shfl_xor_sync(0xffffffffu, mx0, 1));
            mx0 = fmaxf(mx0, __shfl_xor_sync(0xffffffffu, mx0, 2));
            mx1 = fmaxf(mx1, __shfl_xor_sync(0xffffffffu, mx1, 1));
            mx1 = fmaxf(mx1, __shfl_xor_sync(0xffffffffu, mx1, 2));
            const float mn0 = fmaxf(m0r, mx0), mn1 = fmaxf(m1r, mx1);
            const float a0 = __expf(m0r - mn0), a1 = __expf(m1r - mn1);
            m0r = mn0; m1r = mn1;
            float su0 = 0.f, su1 = 0.f;
            #pragma unroll
            for (int j = 0; j < 8; j++) {
                s[j][0] = __expf(s[j][0] - mn0);
                s[j][1] = __expf(s[j][1] - mn0);
                s[j][2] = __expf(s[j][2] - mn1);
                s[j][3] = __expf(s[j][3] - mn1);
                su0 += s[j][0] + s[j][1];
                su1 += s[j][2] + s[j][3];
            }
            su0 += __shfl_xor_sync(0xffffffffu, su0, 1);
            su0 += __shfl_xor_sync(0xffffffffu, su0, 2);
            su1 += __shfl_xor_sync(0xffffffffu, su1, 1);
            su1 += __shfl_xor_sync(0xffffffffu, su1, 2);
            l0r = l0r*a0 + su0;
            l1r = l1r*a1 + su1;
            #pragma unroll
            for (int j = 0; j < 8; j++) {
                o[j][0] *= a0; o[j][1] *= a0; o[j][2] *= a1; o[j][3] *= a1;
            }

            // ---- O += P V ----
            #pragma unroll
            for (int kk = 0; kk < 4; kk++) {
                uint32_t ph[4], pl[4];
                split2(s[2*kk][0],   s[2*kk][1],   ph[0], pl[0]);
                split2(s[2*kk][2],   s[2*kk][3],   ph[1], pl[1]);
                split2(s[2*kk+1][0], s[2*kk+1][1], ph[2], pl[2]);
                split2(s[2*kk+1][2], s[2*kk+1][3], ph[3], pl[3]);
                #pragma unroll
                for (int g = 0; g < 4; g++) {
                    uint32_t vhf[4], vlf[4];
                    const uint32_t vaddr = sVh + (kk*16 + lrq)*ASTRB + g*32 + lch;
                    ldsm4t(vhf, vaddr);
                    ldsm4t(vlf, vaddr + AK_SZ);
                    mma_bf16(o[2*g],   ph, vhf[0], vhf[1]);
                    mma_bf16(o[2*g+1], ph, vhf[2], vhf[3]);
                    mma_bf16(o[2*g],   ph, vlf[0], vlf[1]);
                    mma_bf16(o[2*g+1], ph, vlf[2], vlf[3]);
                    mma_bf16(o[2*g],   pl, vhf[0], vhf[1]);
                    mma_bf16(o[2*g+1], pl, vhf[2], vhf[3]);
                }
            }
        }

        if (t + 1 < nt) CPA_WAIT0();
        __syncthreads();
    }

    // ---- write O split bf16 into [B,S,D] ----
    const float i0 = 1.f / l0r, i1 = 1.f / l1r;
    const int row0 = qs + wid*16 + (lane >> 2);
    const int row1 = row0 + 8;
    const int b = bh >> 4, h = bh & 15;
    #pragma unroll
    for (int j = 0; j < 8; j++) {
        const int c = h*64 + j*8 + (lane & 3)*2;
        const size_t e0 = (size_t)(b*SEQ + row0)*D_MODEL + c;
        const size_t e1 = (size_t)(b*SEQ + row1)*D_MODEL + c;
        uint32_t hi, lo;
        split2(o[j][0]*i0, o[j][1]*i0, hi, lo);
        *(uint32_t*)(Oh_g + e0) = hi;
        *(uint32_t*)(Ol_g + e0) = lo;
        split2(o[j][2]*i1, o[j][3]*i1, hi, lo);
        *(uint32_t*)(Oh_g + e1) = hi;
        *(uint32_t*)(Ol_g + e1) = lo;
    }
}

// =====================================================================
// launch (attn is 4th so ncu's capture slot lands on it)
// =====================================================================
extern "C" void kernel_launch(void* const* d_in, const int* in_sizes, int n_in,
                              void* d_out, int out_size)
{
    (void)in_sizes; (void)n_in; (void)out_size;
    const float* x  = (const float*)d_in[0];
    const float* Wq = (const float*)d_in[1];
    const float* bq = (const float*)d_in[2];
    const float* Wk = (const float*)d_in[3];
    const float* bk = (const float*)d_in[4];
    const float* Wv = (const float*)d_in[5];
    const float* bv = (const float*)d_in[6];
    const float* Wo = (const float*)d_in[7];
    const float* bo = (const float*)d_in[8];
    float* out = (float*)d_out;

    __nv_bfloat16 *xh, *xl, *Wh, *Wl, *Qh, *Ql, *Kh, *Kl, *Vh, *Vl, *Oh, *Ol;
    cudaGetSymbolAddress((void**)&xh, g_xh);
    cudaGetSymbolAddress((void**)&xl, g_xl);
    cudaGetSymbolAddress((void**)&Wh, g_Wh);
    cudaGetSymbolAddress((void**)&Wl, g_Wl);
    cudaGetSymbolAddress((void**)&Qh, g_Qh);
    cudaGetSymbolAddress((void**)&Ql, g_Ql);
    cudaGetSymbolAddress((void**)&Kh, g_Kh);
    cudaGetSymbolAddress((void**)&Kl, g_Kl);
    cudaGetSymbolAddress((void**)&Vh, g_Vh);
    cudaGetSymbolAddress((void**)&Vl, g_Vl);
    cudaGetSymbolAddress((void**)&Oh, g_Oh);
    cudaGetSymbolAddress((void**)&Ol, g_Ol);

    cudaFuncSetAttribute(gemm_qkv,
                         cudaFuncAttributeMaxDynamicSharedMemorySize, GEMM_SMEM);
    cudaFuncSetAttribute(gemm_out,
                         cudaFuncAttributeMaxDynamicSharedMemorySize, GEMM_SMEM);
    cudaFuncSetAttribute(attn_mma,
                         cudaFuncAttributeMaxDynamicSharedMemorySize, ATTN_SMEM);

    // 1) split x
    split4_kernel<<<(MROWS*D_MODEL/4 + 255)/256, 256>>>(x, xh, xl, MROWS*D_MODEL/4);
    // 2) split all four weight matrices
    splitW_kernel<<<dim3(DD/4/256, 4), 256>>>(Wq, Wk, Wv, Wo, Wh, Wl);
    // 3) QKV projections + fused RoPE + split
    gemm_qkv<<<dim3(D_MODEL/128, MROWS/128, 3), 256, GEMM_SMEM>>>(
        xh, xl, Wh, Wl, bq, bk, bv, Qh, Ql, Kh, Kl, Vh, Vl);
    // 4) attention  (ncu capture slot)
    attn_mma<<<dim3(SEQ/128, BHTOT), 256, ATTN_SMEM>>>(
        Qh, Ql, Kh, Kl, Vh, Vl, Oh, Ol);
    // 5) output projection
    gemm_out<<<dim3(D_MODEL/128, MROWS/128), 256, GEMM_SMEM>>>(
        Oh, Ol, Wh + 3*DD, Wl + 3*DD, bo, out);
}